// round 4
// baseline (speedup 1.0000x reference)
#include <cuda_runtime.h>
#include <math.h>

#define TLEN 512
#define NBATCH 32
#define NRSTEP 200
#define BIGV 1e8f

// Per-batch partials: [0..31]=sum_sq, [32..63]=sum_abs, [64..95]=pcc_b, [96..127]=|dtw_b|
__device__ float g_part[4 * NBATCH];

__device__ __forceinline__ float block_sum(float v, float* red) {
    const unsigned full = 0xffffffffu;
#pragma unroll
    for (int o = 16; o > 0; o >>= 1) v += __shfl_down_sync(full, v, o);
    int lane = threadIdx.x & 31;
    int w = threadIdx.x >> 5;
    if (lane == 0) red[w] = v;
    __syncthreads();
    if (w == 0) {
        float t = (lane < 16) ? red[lane] : 0.0f;
#pragma unroll
        for (int o = 8; o > 0; o >>= 1) t += __shfl_down_sync(full, t, o);
        if (lane == 0) red[0] = t;
    }
    __syncthreads();
    float r = red[0];
    __syncthreads();
    return r;
}

__global__ __launch_bounds__(TLEN, 1)
void seqloss_main(const float* __restrict__ pred_map,
                  const int* __restrict__ lat_idx,
                  const float* __restrict__ omega,
                  const float* __restrict__ omni_ts,
                  float* __restrict__ out)
{
    const int b = blockIdx.x;
    const int tid = threadIdx.x;

    __shared__ float sv[2][TLEN];        // HUX double buffer
    __shared__ float xsh[TLEN];          // omni_scaled
    __shared__ float ysh[TLEN];          // v_out_scaled
    __shared__ float diag[3][TLEN + 1];  // rotating anti-diagonals (slot 0 = BIG pad)
    __shared__ float red[16];

    const float dr   = (float)((215.0 - 21.5) * 695700.0 / 200.0);   // 673089.75
    const float dphi = (float)(6.283185307179586476925287 / 512.0);

    const float c = dr * omega[b];

    // ---- gather v_in ----
    const int base = b * TLEN + tid;
    const int lat = lat_idx[base];
    float v = pred_map[base * 128 + lat];

    // ---- HUX: 200 upwind steps with periodic roll(-1) ----
    sv[0][tid] = v;
    __syncthreads();
    int cur = 0;
    for (int k = 0; k < NRSTEP; ++k) {
        float vn = sv[cur][(tid + 1) & (TLEN - 1)];
        float dv = vn - v;
        v = v + c / (fmaxf(v, 1.0f) * dphi) * dv;
        sv[cur ^ 1][tid] = v;
        cur ^= 1;
        __syncthreads();
    }

    // v_out raw to output
    out[base] = v;

    const float vs = (v - 200.0f) / 1000.0f;
    const float os = (omni_ts[base] - 200.0f) / 1000.0f;
    xsh[tid] = os;   // x = omni_scaled
    ysh[tid] = vs;   // y = v_out_scaled
    __syncthreads();

    // ---- per-batch reductions (mae/rmse partials, pcc) ----
    const float diff = vs - os;
    const float s_sq = block_sum(diff * diff, red);
    const float s_ab = block_sum(fabsf(diff), red);
    const float s_v  = block_sum(vs, red);
    const float s_o  = block_sum(os, red);
    const float vmean = s_v * (1.0f / TLEN);
    const float omean = s_o * (1.0f / TLEN);
    const float pc = vs - vmean;
    const float tc = os - omean;
    const float s_nt = block_sum(pc * tc, red);
    const float s_p2 = block_sum(pc * pc, red);
    const float s_t2 = block_sum(tc * tc, red);
    const float pcc_b = s_nt / (sqrtf(s_p2) * sqrtf(s_t2));

    // ---- soft-DTW wavefront over anti-diagonals ----
    // diag buffers: buf[i+1] holds R[row i] of that diagonal; buf[0] = BIG pad.
    diag[0][tid] = BIGV;
    diag[1][tid] = BIGV;
    diag[2][tid] = BIGV;
    if (tid == 0) {
        diag[0][TLEN] = BIGV;
        diag[1][TLEN] = BIGV;
        diag[2][TLEN] = BIGV;
    }
    __syncthreads();
    const float xi = xsh[tid];
    if (tid == 0) {
        float d0 = xi - ysh[0];
        diag[1][1] = d0 * d0;   // R(0,0) = D[0,0]
    }
    __syncthreads();

    int r2i = 0, r1i = 1, rni = 2;
    for (int p = 1; p <= 2 * TLEN - 2; ++p) {
        float rn = BIGV;
        int j = p - tid;
        if (j >= 0 && j < TLEN) {
            float dy = xi - ysh[j];
            float d = dy * dy;
            float up   = diag[r1i][tid];       // R(i-1, j)
            float left = diag[r1i][tid + 1];   // R(i, j-1)
            float dg   = diag[r2i][tid];       // R(i-1, j-1)
            float m = fminf(up, fminf(left, dg));
            // softmin = m - gamma * log( sum exp(-(x-m)/gamma) ), gamma = 0.1
            float s = __expf((m - up) * 10.0f)
                    + __expf((m - left) * 10.0f)
                    + __expf((m - dg) * 10.0f);
            rn = d + m - 0.1f * __logf(s);
        }
        diag[rni][tid + 1] = rn;
        __syncthreads();
        int t = r2i; r2i = r1i; r1i = rni; rni = t;
    }
    const float dtw_b = diag[r1i][TLEN];   // R(T-1, T-1)

    if (tid == 0) {
        g_part[b]              = s_sq;
        g_part[NBATCH + b]     = s_ab;
        g_part[2 * NBATCH + b] = pcc_b;
        g_part[3 * NBATCH + b] = fabsf(dtw_b);
    }
}

__global__ void seqloss_final(float* __restrict__ out)
{
    const int b = threadIdx.x;  // 0..31
    float sq  = g_part[b];
    float ab  = g_part[NBATCH + b];
    float pcc = g_part[2 * NBATCH + b];
    float dtw = g_part[3 * NBATCH + b];
    const unsigned full = 0xffffffffu;
#pragma unroll
    for (int o = 16; o > 0; o >>= 1) {
        sq  += __shfl_down_sync(full, sq, o);
        ab  += __shfl_down_sync(full, ab, o);
        pcc += __shfl_down_sync(full, pcc, o);
        dtw += __shfl_down_sync(full, dtw, o);
    }
    if (b == 0) {
        out[NBATCH * TLEN + 0] = ab;                           // mae_loss
        out[NBATCH * TLEN + 1] = 1.0f - pcc * (1.0f / 32.0f);  // pcc_loss
        out[NBATCH * TLEN + 2] = dtw * (1.0f / 32.0f);         // dtw_loss
        out[NBATCH * TLEN + 3] = sqrtf(sq);                    // rmse_loss
    }
}

extern "C" void kernel_launch(void* const* d_in, const int* in_sizes, int n_in,
                              void* d_out, int out_size) {
    const float* pred_map = (const float*)d_in[0];
    const int*   lat_idx  = (const int*)d_in[1];
    const float* omega    = (const float*)d_in[2];
    const float* omni_ts  = (const float*)d_in[3];
    float* out = (float*)d_out;

    seqloss_main<<<NBATCH, TLEN>>>(pred_map, lat_idx, omega, omni_ts, out);
    seqloss_final<<<1, 32>>>(out);
}